// round 8
// baseline (speedup 1.0000x reference)
#include <cuda_runtime.h>
#include <cuda_bf16.h>

// Problem constants from the reference (MAP = H = W = 64).
#define HH 64
#define WW 64
#define HWSZ 4096
#define MAPC 64
#define NSPLIT 4

// Extract component i (0..7) of two float4s via predicated selects (i is
// warp-uniform -> pure SELs, no divergence, no memory).
__device__ __forceinline__ float comp4(float4 v, int i) {
    float ab = (i & 1) ? v.y : v.x;
    float cd = (i & 1) ? v.w : v.z;
    return (i & 2) ? cd : ab;
}
__device__ __forceinline__ float comp8(float4 a, float4 b, int i) {
    return (i & 4) ? comp4(b, i) : comp4(a, i);
}

// One block per (gt, channel-chunk), 128 threads. FULLY SYNC-FREE:
//  - matching is warp-autonomous: each warp scans all preds lane-strided and
//    __reduce_min_sync gives the complete argmin in every lane. No smem, no
//    __syncthreads, no tid0-serialized section.
//  - dependency chain after the match is 2 exposed latencies, not 3: the
//    offsets load (uniform addr) and the 6 max-window loads (depend only on
//    cy,cx) issue as one batch; only the 4 bilinear loads wait on offsets.
__global__ void __launch_bounds__(128)
rp_kernel(const float* __restrict__ params,
          const float* __restrict__ offsets,
          const int*   __restrict__ vgt_bid,
          const int*   __restrict__ vgt_cen,
          const int*   __restrict__ pred_bid,
          const int*   __restrict__ pred_cyx,
          float* __restrict__ out,
          int n_gt, int n_pred, int C)
{
    const int gt    = blockIdx.x;
    const int chunk = blockIdx.y;
    const int tid   = threadIdx.x;
    const int lane  = tid & 31;

    const int gb = __ldg(&vgt_bid[gt]);
    const int2 gc = ((const int2*)vgt_cen)[gt];
    const int gy = gc.x, gx = gc.y;

    // ---- Phase 1: warp-autonomous matching ----
    const int2* pc2 = (const int2*)pred_cyx;
    unsigned best = 0xFFFFFFFFu;
    #pragma unroll 4
    for (int j = lane; j < n_pred; j += 32) {
        int2 p = pc2[j];
        int dy = p.x - gy;
        int dx = p.y - gx;
        // mismatched batch -> huge-but-finite dist; all-mismatch then yields
        // smallest j (matches jnp.argmin over all-inf returning 0).
        unsigned d2 = (pred_bid[j] == gb) ? (unsigned)(dy * dy + dx * dx)
                                          : 0x00040000u;
        best = min(best, (d2 << 10) | (unsigned)j);   // d2 < 2^18, j < 1024
    }
    best = __reduce_min_sync(0xFFFFFFFFu, best);       // full argmin, all lanes

    const int j  = (int)(best & 1023u);
    const int2 pj = pc2[j];                            // broadcast (1 line)
    const int cy = min(max(pj.x, 0), MAPC - 1);
    const int cx = min(max(pj.y, 0), MAPC - 1);
    const int flat = cy * MAPC + cx;

    if (chunk == 0 && tid == 0) {
        // centers_pred appended after the (n_gt, 2C) block
        out[(size_t)n_gt * 2 * C + 2 * gt]     = (float)(flat % MAPC);
        out[(size_t)n_gt * 2 * C + 2 * gt + 1] = (float)(flat / MAPC);
    }

    const int CH = (C + NSPLIT - 1) / NSPLIT;  // channels per chunk
    const int c  = chunk * CH + tid;
    if (tid >= CH || c >= C) return;

    const float* bp = params + ((size_t)gb * C + c) * HWSZ;

    // ---- Batch 1: offsets (uniform, broadcast) + 6 max-window LDG.128 ----
    const float off_y = __ldg(&offsets[((size_t)gb * 2 + 0) * HWSZ + flat]);
    const float off_x = __ldg(&offsets[((size_t)gb * 2 + 1) * HWSZ + flat]);

    // Max window: 8 cols at 16B-aligned base containing clipped {cx-1,cx,cx+1}.
    const int mbase = min(max(cx - 2, 0), WW - 8) & ~3;
    const int k0 = max(cx - 1, 0)      - mbase;
    const int k1 = cx                  - mbase;
    const int k2 = min(cx + 1, WW - 1) - mbase;
    const int r0 = max(cy - 1, 0);
    const int r1 = cy;
    const int r2 = min(cy + 1, HH - 1);

    const float4* qr0 = (const float4*)(bp + r0 * WW + mbase);
    const float4* qr1 = (const float4*)(bp + r1 * WW + mbase);
    const float4* qr2 = (const float4*)(bp + r2 * WW + mbase);
    float4 m0a = qr0[0], m0b = qr0[1];
    float4 m1a = qr1[0], m1b = qr1[1];
    float4 m2a = qr2[0], m2b = qr2[1];

    // ---- Bilinear geometry (depends on offsets) ----
    const float y = (float)cy + off_y;
    const float x = (float)cx + off_x;
    const float y0f = floorf(y), x0f = floorf(x);
    const float wy1 = y - y0f,   wx1 = x - x0f;
    const float wy0 = 1.f - wy1, wx0 = 1.f - wx1;
    const int yi0 = (int)y0f, xi0 = (int)x0f;
    const bool vx0 = (xi0     >= 0) && (xi0     <= WW - 1);
    const bool vx1 = (xi0 + 1 >= 0) && (xi0 + 1 <= WW - 1);
    const bool vy0 = (yi0     >= 0) && (yi0     <= HH - 1);
    const bool vy1 = (yi0 + 1 >= 0) && (yi0 + 1 <= HH - 1);
    const int by0 = min(max(yi0,     0), HH - 1);
    const int by1 = min(max(yi0 + 1, 0), HH - 1);
    const int bb  = min(max(xi0, 0), WW - 8) & ~3;
    const int j0  = min(max(xi0     - bb, 0), 7);
    const int j1  = min(max(xi0 + 1 - bb, 0), 7);

    // ---- Batch 2: 4 bilinear LDG.128 ----
    const float4* qb0 = (const float4*)(bp + by0 * WW + bb);
    const float4* qb1 = (const float4*)(bp + by1 * WW + bb);
    float4 b0a = qb0[0], b0b = qb0[1];
    float4 b1a = qb1[0], b1b = qb1[1];

    // ---- 3x3 max (registers only) ----
    float mx;
    mx =            comp8(m0a, m0b, k0);
    mx = fmaxf(mx,  comp8(m0a, m0b, k1));
    mx = fmaxf(mx,  comp8(m0a, m0b, k2));
    mx = fmaxf(mx,  comp8(m1a, m1b, k0));
    mx = fmaxf(mx,  comp8(m1a, m1b, k1));
    mx = fmaxf(mx,  comp8(m1a, m1b, k2));
    mx = fmaxf(mx,  comp8(m2a, m2b, k0));
    mx = fmaxf(mx,  comp8(m2a, m2b, k1));
    mx = fmaxf(mx,  comp8(m2a, m2b, k2));

    // ---- bilinear corners, gated by uniform validity (SELs) ----
    float c00 = (vy0 && vx0) ? comp8(b0a, b0b, j0) : 0.f;
    float c01 = (vy0 && vx1) ? comp8(b0a, b0b, j1) : 0.f;
    float c10 = (vy1 && vx0) ? comp8(b1a, b1b, j0) : 0.f;
    float c11 = (vy1 && vx1) ? comp8(b1a, b1b, j1) : 0.f;

    float v = wy0 * wx0 * c00 + wy0 * wx1 * c01
            + wy1 * wx0 * c10 + wy1 * wx1 * c11;

    out[(size_t)gt * 2 * C + c]     = v;   // params_pred (bilinear)
    out[(size_t)gt * 2 * C + C + c] = mx;  // params_pred_max
}

extern "C" void kernel_launch(void* const* d_in, const int* in_sizes, int n_in,
                              void* d_out, int out_size)
{
    const float* params   = (const float*)d_in[0];  // (B, C, 64, 64) f32
    const float* offsets  = (const float*)d_in[1];  // (B, 2, 64, 64) f32
    const int*   vgt_bid  = (const int*)d_in[2];    // (n_gt,)
    const int*   vgt_cen  = (const int*)d_in[3];    // (n_gt, 2)
    const int*   pred_bid = (const int*)d_in[4];    // (n_pred,)
    const int*   pred_cyx = (const int*)d_in[5];    // (n_pred, 2)
    float* out = (float*)d_out;

    const int n_gt   = in_sizes[2];
    const int n_pred = in_sizes[4];
    const int B      = in_sizes[1] / (2 * HWSZ);
    const int C      = in_sizes[0] / (B * HWSZ);

    dim3 grid(n_gt, NSPLIT);
    rp_kernel<<<grid, 128>>>(params, offsets, vgt_bid, vgt_cen,
                             pred_bid, pred_cyx, out, n_gt, n_pred, C);
}

// round 10
// speedup vs baseline: 1.1940x; 1.1940x over previous
#include <cuda_runtime.h>
#include <cuda_bf16.h>

// Problem constants from the reference (MAP = H = W = 64).
#define HH 64
#define WW 64
#define HWSZ 4096
#define MAPC 64
#define NSPLIT 4
#define MAX_GT 1024

// Match records: {batch, flat_ind, bits(y), bits(x)} per gt. Device scratch
// (allowed; no allocation).
__device__ int4 g_match[MAX_GT];

// Extract component i (0..7) of two float4s via predicated selects (i is
// block-uniform -> pure SELs, no divergence, no memory).
__device__ __forceinline__ float comp4(float4 v, int i) {
    float ab = (i & 1) ? v.y : v.x;
    float cd = (i & 1) ? v.w : v.z;
    return (i & 2) ? cd : ab;
}
__device__ __forceinline__ float comp8(float4 a, float4 b, int i) {
    return (i & 4) ? comp4(b, i) : comp4(a, i);
}

// ---------------- k1: matching (one warp per gt) ----------------
__global__ void __launch_bounds__(32)
match_kernel(const float* __restrict__ offsets,
             const int*   __restrict__ vgt_bid,
             const int*   __restrict__ vgt_cen,
             const int*   __restrict__ pred_bid,
             const int*   __restrict__ pred_cyx,
             float* __restrict__ out,
             int n_gt, int n_pred, int C)
{
    const int gt   = blockIdx.x;
    const int lane = threadIdx.x;

    const int gb = __ldg(&vgt_bid[gt]);
    const int2 gc = ((const int2*)vgt_cen)[gt];

    const int2* pc2 = (const int2*)pred_cyx;
    unsigned best = 0xFFFFFFFFu;
    #pragma unroll 4
    for (int j = lane; j < n_pred; j += 32) {
        int2 p = pc2[j];
        int dy = p.x - gc.x;
        int dx = p.y - gc.y;
        // mismatched batch -> huge-but-finite dist; all-mismatch then yields
        // smallest j (matches jnp.argmin over all-inf returning 0).
        unsigned d2 = (pred_bid[j] == gb) ? (unsigned)(dy * dy + dx * dx)
                                          : 0x00040000u;
        best = min(best, (d2 << 10) | (unsigned)j);   // d2 < 2^18, j < 1024
    }
    best = __reduce_min_sync(0xFFFFFFFFu, best);

    const int j  = (int)(best & 1023u);
    const int2 pj = pc2[j];
    const int cy = min(max(pj.x, 0), MAPC - 1);
    const int cx = min(max(pj.y, 0), MAPC - 1);
    const int flat = cy * MAPC + cx;

    // lanes 0,1 fetch the two offset planes in parallel
    float offv = 0.f;
    if (lane < 2)
        offv = offsets[((size_t)gb * 2 + lane) * HWSZ + flat];
    float off_y = __shfl_sync(0xFFFFFFFFu, offv, 0);
    float off_x = __shfl_sync(0xFFFFFFFFu, offv, 1);

    if (lane == 0) {
        int4 rec;
        rec.x = gb;
        rec.y = flat;
        rec.z = __float_as_int((float)cy + off_y);
        rec.w = __float_as_int((float)cx + off_x);
        g_match[gt] = rec;
        // centers_pred appended after the (n_gt, 2C) block
        out[(size_t)n_gt * 2 * C + 2 * gt]     = (float)(flat % MAPC);
        out[(size_t)n_gt * 2 * C + 2 * gt + 1] = (float)(flat / MAPC);
    }
}

// ---------------- k2: gather (no matching, single load batch) ----------------
__global__ void __launch_bounds__(128)
gather_kernel(const float* __restrict__ params,
              float* __restrict__ out,
              int n_gt, int C)
{
    const int gt    = blockIdx.x;
    const int chunk = blockIdx.y;
    const int tid   = threadIdx.x;

    // Uniform 16B record load: replaces matching + broadcast + offsets chain.
    const int4 rec = g_match[gt];
    const int   b    = rec.x;
    const int   flat = rec.y;
    const float y    = __int_as_float(rec.z);
    const float x    = __int_as_float(rec.w);
    const int   cy   = flat >> 6;
    const int   cx   = flat & 63;

    const int CH = (C + NSPLIT - 1) / NSPLIT;
    const int c  = chunk * CH + tid;
    if (tid >= CH || c >= C) return;

    // ---- geometry (all known now; no loads on the path) ----
    // Max window: 8 cols at 16B-aligned base containing clipped {cx-1,cx,cx+1}.
    const int mbase = min(max(cx - 2, 0), WW - 8) & ~3;
    const int k0 = max(cx - 1, 0)      - mbase;
    const int k1 = cx                  - mbase;
    const int k2 = min(cx + 1, WW - 1) - mbase;
    const int r0 = max(cy - 1, 0);
    const int r1 = cy;
    const int r2 = min(cy + 1, HH - 1);

    // Bilinear geometry (zero-fill OOB corners, reference semantics).
    const float y0f = floorf(y), x0f = floorf(x);
    const float wy1 = y - y0f,   wx1 = x - x0f;
    const float wy0 = 1.f - wy1, wx0 = 1.f - wx1;
    const int yi0 = (int)y0f, xi0 = (int)x0f;
    const bool vx0 = (xi0     >= 0) && (xi0     <= WW - 1);
    const bool vx1 = (xi0 + 1 >= 0) && (xi0 + 1 <= WW - 1);
    const bool vy0 = (yi0     >= 0) && (yi0     <= HH - 1);
    const bool vy1 = (yi0 + 1 >= 0) && (yi0 + 1 <= HH - 1);
    const int by0 = min(max(yi0,     0), HH - 1);
    const int by1 = min(max(yi0 + 1, 0), HH - 1);
    const int bb  = min(max(xi0, 0), WW - 8) & ~3;
    const int j0  = min(max(xi0     - bb, 0), 7);
    const int j1  = min(max(xi0 + 1 - bb, 0), 7);

    const float* bp = params + ((size_t)b * C + c) * HWSZ;

    // ---- ONE batch: 10 unconditional independent LDG.128 ----
    const float4* qr0 = (const float4*)(bp + r0 * WW + mbase);
    const float4* qr1 = (const float4*)(bp + r1 * WW + mbase);
    const float4* qr2 = (const float4*)(bp + r2 * WW + mbase);
    const float4* qb0 = (const float4*)(bp + by0 * WW + bb);
    const float4* qb1 = (const float4*)(bp + by1 * WW + bb);
    float4 m0a = qr0[0], m0b = qr0[1];
    float4 m1a = qr1[0], m1b = qr1[1];
    float4 m2a = qr2[0], m2b = qr2[1];
    float4 b0a = qb0[0], b0b = qb0[1];
    float4 b1a = qb1[0], b1b = qb1[1];

    // ---- 3x3 max (registers only) ----
    float mx;
    mx =            comp8(m0a, m0b, k0);
    mx = fmaxf(mx,  comp8(m0a, m0b, k1));
    mx = fmaxf(mx,  comp8(m0a, m0b, k2));
    mx = fmaxf(mx,  comp8(m1a, m1b, k0));
    mx = fmaxf(mx,  comp8(m1a, m1b, k1));
    mx = fmaxf(mx,  comp8(m1a, m1b, k2));
    mx = fmaxf(mx,  comp8(m2a, m2b, k0));
    mx = fmaxf(mx,  comp8(m2a, m2b, k1));
    mx = fmaxf(mx,  comp8(m2a, m2b, k2));

    // ---- bilinear corners, gated by uniform validity (SELs) ----
    float c00 = (vy0 && vx0) ? comp8(b0a, b0b, j0) : 0.f;
    float c01 = (vy0 && vx1) ? comp8(b0a, b0b, j1) : 0.f;
    float c10 = (vy1 && vx0) ? comp8(b1a, b1b, j0) : 0.f;
    float c11 = (vy1 && vx1) ? comp8(b1a, b1b, j1) : 0.f;

    float v = wy0 * wx0 * c00 + wy0 * wx1 * c01
            + wy1 * wx0 * c10 + wy1 * wx1 * c11;

    out[(size_t)gt * 2 * C + c]     = v;   // params_pred (bilinear)
    out[(size_t)gt * 2 * C + C + c] = mx;  // params_pred_max
}

extern "C" void kernel_launch(void* const* d_in, const int* in_sizes, int n_in,
                              void* d_out, int out_size)
{
    const float* params   = (const float*)d_in[0];  // (B, C, 64, 64) f32
    const float* offsets  = (const float*)d_in[1];  // (B, 2, 64, 64) f32
    const int*   vgt_bid  = (const int*)d_in[2];    // (n_gt,)
    const int*   vgt_cen  = (const int*)d_in[3];    // (n_gt, 2)
    const int*   pred_bid = (const int*)d_in[4];    // (n_pred,)
    const int*   pred_cyx = (const int*)d_in[5];    // (n_pred, 2)
    float* out = (float*)d_out;

    const int n_gt   = in_sizes[2];
    const int n_pred = in_sizes[4];
    const int B      = in_sizes[1] / (2 * HWSZ);
    const int C      = in_sizes[0] / (B * HWSZ);

    match_kernel<<<n_gt, 32>>>(offsets, vgt_bid, vgt_cen,
                               pred_bid, pred_cyx, out, n_gt, n_pred, C);
    dim3 grid(n_gt, NSPLIT);
    gather_kernel<<<grid, 128>>>(params, out, n_gt, C);
}

// round 12
// speedup vs baseline: 1.4388x; 1.2050x over previous
#include <cuda_runtime.h>
#include <cuda_bf16.h>

// Problem constants from the reference (MAP = H = W = 64).
#define HH 64
#define WW 64
#define HWSZ 4096
#define MAPC 64
#define NSPLIT 4

// Extract component i (0..7) of two float4s via predicated selects (i is
// block-uniform -> pure SELs, no divergence, no memory).
__device__ __forceinline__ float comp4(float4 v, int i) {
    float ab = (i & 1) ? v.y : v.x;
    float cd = (i & 1) ? v.w : v.z;
    return (i & 2) ? cd : ab;
}
__device__ __forceinline__ float comp8(float4 a, float4 b, int i) {
    return (i & 4) ? comp4(b, i) : comp4(a, i);
}

// Fused single kernel (two-kernel split costs ~2us in graph node overhead).
// 256 threads/block, grid (n_gt, NSPLIT). ROLE SPLIT to double occupancy
// (R10 showed occ=18% / nothing saturated -> parallelism-starved latency
// bound): warps 0-3 compute the bilinear sample (4 LDG.128 + offsets),
// warps 4-7 compute the 3x3 max (6 LDG.128, no offsets dependency).
// 4096 warps total -> ~28/SM (~36% occ), half-size load batches per warp.
__global__ void __launch_bounds__(256)
rp_kernel(const float* __restrict__ params,
          const float* __restrict__ offsets,
          const int*   __restrict__ vgt_bid,
          const int*   __restrict__ vgt_cen,
          const int*   __restrict__ pred_bid,
          const int*   __restrict__ pred_cyx,
          float* __restrict__ out,
          int n_gt, int n_pred, int C)
{
    const int gt    = blockIdx.x;
    const int chunk = blockIdx.y;
    const int tid   = threadIdx.x;

    __shared__ unsigned s_warpmin[8];
    __shared__ int s_b, s_flat;

    const int gb = __ldg(&vgt_bid[gt]);
    const int2 gc = ((const int2*)vgt_cen)[gt];

    // ---- Phase 1: matching (256 threads, 2 iterations each) ----
    const int2* pc2 = (const int2*)pred_cyx;
    unsigned best = 0xFFFFFFFFu;
    for (int j = tid; j < n_pred; j += blockDim.x) {
        int2 p = pc2[j];
        int dy = p.x - gc.x;
        int dx = p.y - gc.y;
        // mismatched batch -> huge-but-finite dist; all-mismatch then yields
        // smallest j (matches jnp.argmin over all-inf returning 0).
        unsigned d2 = (pred_bid[j] == gb) ? (unsigned)(dy * dy + dx * dx)
                                          : 0x00040000u;
        best = min(best, (d2 << 10) | (unsigned)j);   // d2 < 2^18, j < 1024
    }
    best = __reduce_min_sync(0xFFFFFFFFu, best);
    if ((tid & 31) == 0) s_warpmin[tid >> 5] = best;
    __syncthreads();
    if (tid == 0) {
        unsigned m = s_warpmin[0];
        #pragma unroll
        for (int w = 1; w < 8; w++) m = min(m, s_warpmin[w]);
        int j  = (int)(m & 1023u);
        int2 p = pc2[j];
        int py = min(max(p.x, 0), MAPC - 1);
        int px = min(max(p.y, 0), MAPC - 1);
        int flat = py * MAPC + px;
        s_b    = gb;
        s_flat = flat;
        if (chunk == 0) {
            // centers_pred appended after the (n_gt, 2C) block
            out[(size_t)n_gt * 2 * C + 2 * gt]     = (float)(flat % MAPC);
            out[(size_t)n_gt * 2 * C + 2 * gt + 1] = (float)(flat / MAPC);
        }
    }
    __syncthreads();

    const int b    = s_b;
    const int flat = s_flat;
    const int cy   = flat >> 6;
    const int cx   = flat & 63;

    const int CH   = (C + NSPLIT - 1) / NSPLIT;   // 100 channels per chunk
    const int role = tid >> 7;                    // warp-uniform: 0=bilinear, 1=max
    const int ci   = tid & 127;
    const int c    = chunk * CH + ci;
    if (ci >= CH || c >= C) return;

    const float* bp = params + ((size_t)b * C + c) * HWSZ;

    if (role == 1) {
        // ---------- 3x3 max: 6 unconditional LDG.128, one batch ----------
        const int mbase = min(max(cx - 2, 0), WW - 8) & ~3;
        const int k0 = max(cx - 1, 0)      - mbase;
        const int k1 = cx                  - mbase;
        const int k2 = min(cx + 1, WW - 1) - mbase;
        const int r0 = max(cy - 1, 0);
        const int r2 = min(cy + 1, HH - 1);

        const float4* qr0 = (const float4*)(bp + r0 * WW + mbase);
        const float4* qr1 = (const float4*)(bp + cy * WW + mbase);
        const float4* qr2 = (const float4*)(bp + r2 * WW + mbase);
        float4 m0a = qr0[0], m0b = qr0[1];
        float4 m1a = qr1[0], m1b = qr1[1];
        float4 m2a = qr2[0], m2b = qr2[1];

        float mx;
        mx =            comp8(m0a, m0b, k0);
        mx = fmaxf(mx,  comp8(m0a, m0b, k1));
        mx = fmaxf(mx,  comp8(m0a, m0b, k2));
        mx = fmaxf(mx,  comp8(m1a, m1b, k0));
        mx = fmaxf(mx,  comp8(m1a, m1b, k1));
        mx = fmaxf(mx,  comp8(m1a, m1b, k2));
        mx = fmaxf(mx,  comp8(m2a, m2b, k0));
        mx = fmaxf(mx,  comp8(m2a, m2b, k1));
        mx = fmaxf(mx,  comp8(m2a, m2b, k2));

        out[(size_t)gt * 2 * C + C + c] = mx;     // params_pred_max
    } else {
        // ---------- bilinear: offsets (broadcast) then 4 LDG.128 ----------
        const float off_y = __ldg(&offsets[((size_t)b * 2 + 0) * HWSZ + flat]);
        const float off_x = __ldg(&offsets[((size_t)b * 2 + 1) * HWSZ + flat]);
        const float y = (float)cy + off_y;
        const float x = (float)cx + off_x;

        const float y0f = floorf(y), x0f = floorf(x);
        const float wy1 = y - y0f,   wx1 = x - x0f;
        const float wy0 = 1.f - wy1, wx0 = 1.f - wx1;
        const int yi0 = (int)y0f, xi0 = (int)x0f;
        const bool vx0 = (xi0     >= 0) && (xi0     <= WW - 1);
        const bool vx1 = (xi0 + 1 >= 0) && (xi0 + 1 <= WW - 1);
        const bool vy0 = (yi0     >= 0) && (yi0     <= HH - 1);
        const bool vy1 = (yi0 + 1 >= 0) && (yi0 + 1 <= HH - 1);
        const int by0 = min(max(yi0,     0), HH - 1);
        const int by1 = min(max(yi0 + 1, 0), HH - 1);
        const int bb  = min(max(xi0, 0), WW - 8) & ~3;
        const int j0  = min(max(xi0     - bb, 0), 7);
        const int j1  = min(max(xi0 + 1 - bb, 0), 7);

        const float4* qb0 = (const float4*)(bp + by0 * WW + bb);
        const float4* qb1 = (const float4*)(bp + by1 * WW + bb);
        float4 b0a = qb0[0], b0b = qb0[1];
        float4 b1a = qb1[0], b1b = qb1[1];

        float c00 = (vy0 && vx0) ? comp8(b0a, b0b, j0) : 0.f;
        float c01 = (vy0 && vx1) ? comp8(b0a, b0b, j1) : 0.f;
        float c10 = (vy1 && vx0) ? comp8(b1a, b1b, j0) : 0.f;
        float c11 = (vy1 && vx1) ? comp8(b1a, b1b, j1) : 0.f;

        float v = wy0 * wx0 * c00 + wy0 * wx1 * c01
                + wy1 * wx0 * c10 + wy1 * wx1 * c11;

        out[(size_t)gt * 2 * C + c] = v;          // params_pred (bilinear)
    }
}

extern "C" void kernel_launch(void* const* d_in, const int* in_sizes, int n_in,
                              void* d_out, int out_size)
{
    const float* params   = (const float*)d_in[0];  // (B, C, 64, 64) f32
    const float* offsets  = (const float*)d_in[1];  // (B, 2, 64, 64) f32
    const int*   vgt_bid  = (const int*)d_in[2];    // (n_gt,)
    const int*   vgt_cen  = (const int*)d_in[3];    // (n_gt, 2)
    const int*   pred_bid = (const int*)d_in[4];    // (n_pred,)
    const int*   pred_cyx = (const int*)d_in[5];    // (n_pred, 2)
    float* out = (float*)d_out;

    const int n_gt   = in_sizes[2];
    const int n_pred = in_sizes[4];
    const int B      = in_sizes[1] / (2 * HWSZ);
    const int C      = in_sizes[0] / (B * HWSZ);

    dim3 grid(n_gt, NSPLIT);
    rp_kernel<<<grid, 256>>>(params, offsets, vgt_bid, vgt_cen,
                             pred_bid, pred_cyx, out, n_gt, n_pred, C);
}